// round 1
// baseline (speedup 1.0000x reference)
#include <cuda_runtime.h>
#include <cuda_bf16.h>
#include <math.h>

#define EPS 1e-5f

static const int F = 128;        // features (x is [N,128])
static const int F4 = 32;        // float4 per row
static const int GMAX = 1024;    // >= actual batch_size (256); extra segs are benign

// Scratch (no allocations allowed): ~2.3 MB of __device__ globals.
__device__ float g_s1[GMAX * F];
__device__ float g_s2[GMAX * F];
__device__ float g_cnt[GMAX];
__device__ float g_mean[GMAX * F];
__device__ float g_rstd[GMAX * F];

// ---------------------------------------------------------------------------
// 0) zero the accumulators
// ---------------------------------------------------------------------------
__global__ void zero_kernel() {
    int total = 2 * GMAX * F + GMAX;
    for (int i = blockIdx.x * blockDim.x + threadIdx.x; i < total;
         i += gridDim.x * blockDim.x) {
        if (i < GMAX * F)            g_s1[i] = 0.f;
        else if (i < 2 * GMAX * F)   g_s2[i - GMAX * F] = 0.f;
        else                         g_cnt[i - 2 * GMAX * F] = 0.f;
    }
}

// ---------------------------------------------------------------------------
// 1) per-segment sum / sumsq. batch is SORTED, so each block's contiguous row
//    chunk touches only 1-2 segments: accumulate in registers, flush on
//    segment change via atomicAdd. blockDim = 512: 4 "row lanes" x 128 features.
// ---------------------------------------------------------------------------
__global__ void __launch_bounds__(512) stats_kernel(
    const float* __restrict__ x, const int* __restrict__ batch,
    int N, int rows_per_block)
{
    const int f  = threadIdx.x & (F - 1);   // feature 0..127
    const int rl = threadIdx.x >> 7;        // row lane 0..3

    const int row0    = blockIdx.x * rows_per_block;
    const int row_end = min(N, row0 + rows_per_block);
    if (row0 >= N) return;

    float s1 = 0.f, s2 = 0.f, cnt = 0.f;
    int cur = -1;

#define GN_FLUSH()                                                      \
    do {                                                                \
        if (cur >= 0) {                                                 \
            atomicAdd(&g_s1[cur * F + f], s1);                          \
            atomicAdd(&g_s2[cur * F + f], s2);                          \
            if (f == 0) atomicAdd(&g_cnt[cur], cnt);                    \
        }                                                               \
    } while (0)

#define GN_PROC(SEG, V)                                                 \
    do {                                                                \
        if ((SEG) != cur) {                                             \
            GN_FLUSH();                                                 \
            cur = (SEG); s1 = 0.f; s2 = 0.f; cnt = 0.f;                 \
        }                                                               \
        s1 += (V); s2 += (V) * (V); cnt += 1.f;                         \
    } while (0)

    int r = row0 + rl;
    // main body: prefetch 4 iterations (MLP = 8 loads/thread in flight)
    for (; r + 12 < row_end; r += 16) {
        const int  sA = batch[r];
        const int  sB = batch[r + 4];
        const int  sC = batch[r + 8];
        const int  sD = batch[r + 12];
        const float vA = x[(size_t)r * F + f];
        const float vB = x[(size_t)(r + 4) * F + f];
        const float vC = x[(size_t)(r + 8) * F + f];
        const float vD = x[(size_t)(r + 12) * F + f];
        GN_PROC(sA, vA);
        GN_PROC(sB, vB);
        GN_PROC(sC, vC);
        GN_PROC(sD, vD);
    }
    // tail
    for (; r < row_end; r += 4) {
        const int   seg = batch[r];
        const float v   = x[(size_t)r * F + f];
        GN_PROC(seg, v);
    }
    GN_FLUSH();
#undef GN_PROC
#undef GN_FLUSH
}

// ---------------------------------------------------------------------------
// 2) finalize: mean + rstd tables (G*F = 32K each, L2-resident in pass 3)
// ---------------------------------------------------------------------------
__global__ void finalize_kernel() {
    int idx = blockIdx.x * blockDim.x + threadIdx.x;
    if (idx >= GMAX * F) return;
    const int g = idx >> 7;
    const float c     = g_cnt[g];
    const float denom = fmaxf(c, 1.f);
    const float mean  = g_s1[idx] / denom;
    float var = g_s2[idx] / denom - mean * mean;
    var = fmaxf(var, EPS);
    g_mean[idx] = mean;
    g_rstd[idx] = rsqrtf(var + EPS);
}

// ---------------------------------------------------------------------------
// 3) normalize: float4; each warp == exactly one row, so batch[row] is a
//    single broadcast sector per warp. mean/rstd/gamma/beta all hit L2/L1.
// ---------------------------------------------------------------------------
__global__ void __launch_bounds__(256) norm_kernel(
    const float4* __restrict__ x4, const int* __restrict__ batch,
    const float4* __restrict__ gamma4, const float4* __restrict__ beta4,
    float4* __restrict__ out4, int total4)
{
    const float4* __restrict__ mean4 = (const float4*)g_mean;
    const float4* __restrict__ rstd4 = (const float4*)g_rstd;

    int i      = blockIdx.x * blockDim.x + threadIdx.x;
    int stride = gridDim.x * blockDim.x;
#pragma unroll 4
    for (; i < total4; i += stride) {
        const int row = i >> 5;       // F4 = 32 float4 per row
        const int c   = i & 31;
        const int seg = batch[row];
        const float4 v  = x4[i];
        const float4 m  = mean4[seg * F4 + c];
        const float4 rs = rstd4[seg * F4 + c];
        const float4 gm = gamma4[c];
        const float4 bt = beta4[c];
        float4 o;
        o.x = (v.x - m.x) * rs.x * gm.x + bt.x;
        o.y = (v.y - m.y) * rs.y * gm.y + bt.y;
        o.z = (v.z - m.z) * rs.z * gm.z + bt.z;
        o.w = (v.w - m.w) * rs.w * gm.w + bt.w;
        out4[i] = o;
    }
}

// ---------------------------------------------------------------------------
extern "C" void kernel_launch(void* const* d_in, const int* in_sizes, int n_in,
                              void* d_out, int out_size)
{
    const float* x     = (const float*)d_in[0];
    const float* gamma = (const float*)d_in[1];
    const float* beta  = (const float*)d_in[2];
    const int*   batch = (const int*)d_in[3];
    // d_in[4] = batch_size (device scalar); GMAX covers it statically.

    const int N = in_sizes[3];          // rows
    // F fixed at 128 per problem shape (in_sizes[1] == 128).

    // 0) zero accumulators
    zero_kernel<<<256, 256>>>();

    // 1) stats
    const int stat_blocks = 2368;       // 148 SMs * 16
    const int rows_per_block = (N + stat_blocks - 1) / stat_blocks;
    stats_kernel<<<stat_blocks, 512>>>(x, batch, N, rows_per_block);

    // 2) finalize mean/rstd
    finalize_kernel<<<(GMAX * F + 255) / 256, 256>>>();

    // 3) normalize
    const int total4 = N * F4;
    const int norm_blocks = 148 * 32;
    norm_kernel<<<norm_blocks, 256>>>((const float4*)x, batch,
                                      (const float4*)gamma, (const float4*)beta,
                                      (float4*)d_out, total4);
}

// round 5
// speedup vs baseline: 1.2008x; 1.2008x over previous
#include <cuda_runtime.h>
#include <cuda_bf16.h>
#include <math.h>

#define EPS 1e-5f

static const int F = 128;        // features (x is [N,128])
static const int F4 = 32;        // float4 per row
static const int GMAX = 1024;    // >= actual batch_size (256)

// Scratch (no allocations allowed): __device__ globals.
__device__ float g_s1[GMAX * F];
__device__ float g_s2[GMAX * F];
__device__ float g_cnt[GMAX];
__device__ float g_mean[GMAX * F];
__device__ float g_rstd[GMAX * F];

// ---------------------------------------------------------------------------
// 0) zero the accumulators
// ---------------------------------------------------------------------------
__global__ void zero_kernel() {
    int total = 2 * GMAX * F + GMAX;
    for (int i = blockIdx.x * blockDim.x + threadIdx.x; i < total;
         i += gridDim.x * blockDim.x) {
        if (i < GMAX * F)            g_s1[i] = 0.f;
        else if (i < 2 * GMAX * F)   g_s2[i - GMAX * F] = 0.f;
        else                         g_cnt[i - 2 * GMAX * F] = 0.f;
    }
}

// ---------------------------------------------------------------------------
// 1) per-segment sum/sumsq. batch sorted -> register accumulation, flush on
//    segment change. 512 threads = 4 row lanes x 128 features.
//    8 row-groups prefetched per main-loop iteration (16 loads in flight).
// ---------------------------------------------------------------------------
__global__ void __launch_bounds__(512) stats_kernel(
    const float* __restrict__ x, const int* __restrict__ batch,
    int N, int rows_per_block)
{
    const int f  = threadIdx.x & (F - 1);
    const int rl = threadIdx.x >> 7;

    const int row0    = blockIdx.x * rows_per_block;
    const int row_end = min(N, row0 + rows_per_block);
    if (row0 >= N) return;

    float s1 = 0.f, s2 = 0.f, cnt = 0.f;
    int cur = -1;

#define GN_FLUSH()                                                      \
    do {                                                                \
        if (cur >= 0) {                                                 \
            atomicAdd(&g_s1[cur * F + f], s1);                          \
            atomicAdd(&g_s2[cur * F + f], s2);                          \
            if (f == 0) atomicAdd(&g_cnt[cur], cnt);                    \
        }                                                               \
    } while (0)

#define GN_PROC(SEG, V)                                                 \
    do {                                                                \
        if ((SEG) != cur) {                                             \
            GN_FLUSH();                                                 \
            cur = (SEG); s1 = 0.f; s2 = 0.f; cnt = 0.f;                 \
        }                                                               \
        s1 += (V); s2 += (V) * (V); cnt += 1.f;                         \
    } while (0)

    int r = row0 + rl;
    // main body: 8 row-groups in flight per thread
    for (; r + 28 < row_end; r += 32) {
        int   sg[8];
        float vv[8];
#pragma unroll
        for (int k = 0; k < 8; k++) sg[k] = __ldg(&batch[r + 4 * k]);
#pragma unroll
        for (int k = 0; k < 8; k++) vv[k] = __ldcs(&x[(size_t)(r + 4 * k) * F + f]);
#pragma unroll
        for (int k = 0; k < 8; k++) GN_PROC(sg[k], vv[k]);
    }
    for (; r < row_end; r += 4) {
        const int   seg = __ldg(&batch[r]);
        const float v   = __ldcs(&x[(size_t)r * F + f]);
        GN_PROC(seg, v);
    }
    GN_FLUSH();
#undef GN_PROC
#undef GN_FLUSH
}

// ---------------------------------------------------------------------------
// 2) finalize: mean + rstd tables (L2-resident in pass 3)
// ---------------------------------------------------------------------------
__global__ void finalize_kernel() {
    int idx = blockIdx.x * blockDim.x + threadIdx.x;
    if (idx >= GMAX * F) return;
    const int g = idx >> 7;
    const float c     = g_cnt[g];
    const float denom = fmaxf(c, 1.f);
    const float mean  = g_s1[idx] / denom;
    float var = g_s2[idx] / denom - mean * mean;
    var = fmaxf(var, EPS);
    g_mean[idx] = mean;
    g_rstd[idx] = rsqrtf(var + EPS);
}

// ---------------------------------------------------------------------------
// 3) normalize: float4, warp == one row. Manual 4x strided unroll with
//    front-batched independent loads (high MLP_p1), streaming hints so
//    batch + mean/rstd tables stay L2-resident.
// ---------------------------------------------------------------------------
__global__ void __launch_bounds__(256) norm_kernel(
    const float4* __restrict__ x4, const int* __restrict__ batch,
    const float4* __restrict__ gamma4, const float4* __restrict__ beta4,
    float4* __restrict__ out4, int total4)
{
    const float4* __restrict__ mean4 = (const float4*)g_mean;
    const float4* __restrict__ rstd4 = (const float4*)g_rstd;

    const int stride = gridDim.x * blockDim.x;
    int i = blockIdx.x * blockDim.x + threadIdx.x;

    for (; i + 3 * stride < total4; i += 4 * stride) {
        const int iA = i, iB = i + stride, iC = i + 2 * stride, iD = i + 3 * stride;
        // independent index loads, front-batched
        const int sA = __ldg(&batch[iA >> 5]);
        const int sB = __ldg(&batch[iB >> 5]);
        const int sC = __ldg(&batch[iC >> 5]);
        const int sD = __ldg(&batch[iD >> 5]);
        const float4 vA = __ldcs(&x4[iA]);
        const float4 vB = __ldcs(&x4[iB]);
        const float4 vC = __ldcs(&x4[iC]);
        const float4 vD = __ldcs(&x4[iD]);
        const int cA = iA & 31, cB = iB & 31, cC = iC & 31, cD = iD & 31;
        const float4 mA = __ldg(&mean4[sA * F4 + cA]);
        const float4 mB = __ldg(&mean4[sB * F4 + cB]);
        const float4 mC = __ldg(&mean4[sC * F4 + cC]);
        const float4 mD = __ldg(&mean4[sD * F4 + cD]);
        const float4 rA = __ldg(&rstd4[sA * F4 + cA]);
        const float4 rB = __ldg(&rstd4[sB * F4 + cB]);
        const float4 rC = __ldg(&rstd4[sC * F4 + cC]);
        const float4 rD = __ldg(&rstd4[sD * F4 + cD]);
        const float4 gA = __ldg(&gamma4[cA]);
        const float4 gB = __ldg(&gamma4[cB]);
        const float4 gC = __ldg(&gamma4[cC]);
        const float4 gD = __ldg(&gamma4[cD]);
        const float4 bA = __ldg(&beta4[cA]);
        const float4 bB = __ldg(&beta4[cB]);
        const float4 bC = __ldg(&beta4[cC]);
        const float4 bD = __ldg(&beta4[cD]);
        float4 o;
        o.x = (vA.x - mA.x) * rA.x * gA.x + bA.x;
        o.y = (vA.y - mA.y) * rA.y * gA.y + bA.y;
        o.z = (vA.z - mA.z) * rA.z * gA.z + bA.z;
        o.w = (vA.w - mA.w) * rA.w * gA.w + bA.w;
        __stcs(&out4[iA], o);
        o.x = (vB.x - mB.x) * rB.x * gB.x + bB.x;
        o.y = (vB.y - mB.y) * rB.y * gB.y + bB.y;
        o.z = (vB.z - mB.z) * rB.z * gB.z + bB.z;
        o.w = (vB.w - mB.w) * rB.w * gB.w + bB.w;
        __stcs(&out4[iB], o);
        o.x = (vC.x - mC.x) * rC.x * gC.x + bC.x;
        o.y = (vC.y - mC.y) * rC.y * gC.y + bC.y;
        o.z = (vC.z - mC.z) * rC.z * gC.z + bC.z;
        o.w = (vC.w - mC.w) * rC.w * gC.w + bC.w;
        __stcs(&out4[iC], o);
        o.x = (vD.x - mD.x) * rD.x * gD.x + bD.x;
        o.y = (vD.y - mD.y) * rD.y * gD.y + bD.y;
        o.z = (vD.z - mD.z) * rD.z * gD.z + bD.z;
        o.w = (vD.w - mD.w) * rD.w * gD.w + bD.w;
        __stcs(&out4[iD], o);
    }
    // remainder
    for (; i < total4; i += stride) {
        const int row = i >> 5;
        const int c   = i & 31;
        const int seg = __ldg(&batch[row]);
        const float4 v  = __ldcs(&x4[i]);
        const float4 m  = __ldg(&mean4[seg * F4 + c]);
        const float4 rs = __ldg(&rstd4[seg * F4 + c]);
        const float4 gm = __ldg(&gamma4[c]);
        const float4 bt = __ldg(&beta4[c]);
        float4 o;
        o.x = (v.x - m.x) * rs.x * gm.x + bt.x;
        o.y = (v.y - m.y) * rs.y * gm.y + bt.y;
        o.z = (v.z - m.z) * rs.z * gm.z + bt.z;
        o.w = (v.w - m.w) * rs.w * gm.w + bt.w;
        __stcs(&out4[i], o);
    }
}

// ---------------------------------------------------------------------------
extern "C" void kernel_launch(void* const* d_in, const int* in_sizes, int n_in,
                              void* d_out, int out_size)
{
    const float* x     = (const float*)d_in[0];
    const float* gamma = (const float*)d_in[1];
    const float* beta  = (const float*)d_in[2];
    const int*   batch = (const int*)d_in[3];

    const int N = in_sizes[3];

    zero_kernel<<<256, 256>>>();

    const int stat_blocks = 2368;       // 148 SMs * 16
    const int rows_per_block = (N + stat_blocks - 1) / stat_blocks;
    stats_kernel<<<stat_blocks, 512>>>(x, batch, N, rows_per_block);

    finalize_kernel<<<(GMAX * F + 255) / 256, 256>>>();

    const int total4 = N * F4;
    const int norm_blocks = 148 * 32;
    norm_kernel<<<norm_blocks, 256>>>((const float4*)x, batch,
                                      (const float4*)gamma, (const float4*)beta,
                                      (float4*)d_out, total4);
}